// round 16
// baseline (speedup 1.0000x reference)
#include <cuda_runtime.h>

#define D_MODEL  1024
#define N_HEADS  16
#define HEAD_DIM 64
#define SEQ      2048
#define BATCH    2
#define M_ROWS   (BATCH * SEQ)   // 4096

typedef unsigned long long u64;

// ---- packed f32x2 helpers (sm_103a dual fp32 path; ptxas never auto-emits) ----
__device__ __forceinline__ u64 pk2(float lo, float hi) {
    u64 r; asm("mov.b64 %0, {%1, %2};" : "=l"(r) : "f"(lo), "f"(hi)); return r;
}
__device__ __forceinline__ void up2(u64 v, float& lo, float& hi) {
    asm("mov.b64 {%0, %1}, %2;" : "=f"(lo), "=f"(hi) : "l"(v));
}
__device__ __forceinline__ void f2fma(u64& d, u64 a, u64 b) {
    asm("fma.rn.f32x2 %0, %1, %2, %0;" : "+l"(d) : "l"(a), "l"(b));
}
__device__ __forceinline__ void f2mul(u64& d, u64 a) {
    asm("mul.rn.f32x2 %0, %0, %1;" : "+l"(d) : "l"(a));
}

// Scratch (device globals: allocation-free per harness rules)
__device__ float g_q[M_ROWS * D_MODEL];
__device__ float g_k[M_ROWS * D_MODEL];
__device__ float g_v[M_ROWS * D_MODEL];
__device__ float g_y[M_ROWS * D_MODEL];

// ---------------------------------------------------------------------------
// NT GEMM: Y = X @ W^T + bias.   X:[M,K], W:[N,K], bias:[N]
// 128x128x8 tiles, 256 threads, 8x8 per thread, double-buffered SMEM.
// Inner product in packed f32x2: acc paired over i (adjacent in float4 A frag),
// B operand duplicated into both halves.
// ---------------------------------------------------------------------------
__global__ void __launch_bounds__(256) sgemm_nt(
    const float* __restrict__ X, const float* __restrict__ W,
    const float* __restrict__ bias, float* __restrict__ Y,
    int M, int N, int K, int splitHeads)
{
    __shared__ float As[2][8][128];
    __shared__ float Bs[2][8][128];

    const int tid = threadIdx.x;
    const int tx  = tid & 15;          // 0..15 (n groups)
    const int ty  = tid >> 4;          // 0..15 (m groups)
    const int m0  = blockIdx.y * 128;
    const int n0  = blockIdx.x * 128;

    const int lrow = tid >> 1;         // 0..127
    const int lseg = (tid & 1) * 4;    // 0 or 4

    const float* Xp = X + (m0 + lrow) * K + lseg;
    const float* Wp = W + (n0 + lrow) * K + lseg;

    float4 xa = *(const float4*)Xp;
    float4 wb = *(const float4*)Wp;

    As[0][lseg + 0][lrow] = xa.x;
    As[0][lseg + 1][lrow] = xa.y;
    As[0][lseg + 2][lrow] = xa.z;
    As[0][lseg + 3][lrow] = xa.w;
    Bs[0][lseg + 0][lrow] = wb.x;
    Bs[0][lseg + 1][lrow] = wb.y;
    Bs[0][lseg + 2][lrow] = wb.z;
    Bs[0][lseg + 3][lrow] = wb.w;
    __syncthreads();

    u64 acc2[4][8];   // acc2[ip][j] = (acc[2ip][j], acc[2ip+1][j])
#pragma unroll
    for (int ip = 0; ip < 4; ++ip)
#pragma unroll
        for (int j = 0; j < 8; ++j) acc2[ip][j] = 0ull;

    const int ntiles = K >> 3;
    int buf = 0;
    for (int t = 0; t < ntiles; ++t) {
        if (t + 1 < ntiles) {
            xa = *(const float4*)(Xp + (t + 1) * 8);
            wb = *(const float4*)(Wp + (t + 1) * 8);
        }
#pragma unroll
        for (int k = 0; k < 8; ++k) {
            float4 a0 = *(const float4*)(&As[buf][k][ty * 4]);
            float4 a1 = *(const float4*)(&As[buf][k][ty * 4 + 64]);
            float4 b0 = *(const float4*)(&Bs[buf][k][tx * 4]);
            float4 b1 = *(const float4*)(&Bs[buf][k][tx * 4 + 64]);
            u64 ap[4] = { pk2(a0.x, a0.y), pk2(a0.z, a0.w),
                          pk2(a1.x, a1.y), pk2(a1.z, a1.w) };
            u64 bd[8] = { pk2(b0.x, b0.x), pk2(b0.y, b0.y),
                          pk2(b0.z, b0.z), pk2(b0.w, b0.w),
                          pk2(b1.x, b1.x), pk2(b1.y, b1.y),
                          pk2(b1.z, b1.z), pk2(b1.w, b1.w) };
#pragma unroll
            for (int ip = 0; ip < 4; ++ip)
#pragma unroll
                for (int j = 0; j < 8; ++j)
                    f2fma(acc2[ip][j], ap[ip], bd[j]);
        }
        if (t + 1 < ntiles) {
            buf ^= 1;
            As[buf][lseg + 0][lrow] = xa.x;
            As[buf][lseg + 1][lrow] = xa.y;
            As[buf][lseg + 2][lrow] = xa.z;
            As[buf][lseg + 3][lrow] = xa.w;
            Bs[buf][lseg + 0][lrow] = wb.x;
            Bs[buf][lseg + 1][lrow] = wb.y;
            Bs[buf][lseg + 2][lrow] = wb.z;
            Bs[buf][lseg + 3][lrow] = wb.w;
            __syncthreads();
        }
    }

    // unpack accumulators
    float accf[8][8];
#pragma unroll
    for (int ip = 0; ip < 4; ++ip)
#pragma unroll
        for (int j = 0; j < 8; ++j)
            up2(acc2[ip][j], accf[2 * ip][j], accf[2 * ip + 1][j]);

    // epilogue
#pragma unroll
    for (int ih = 0; ih < 2; ++ih) {
#pragma unroll
        for (int r = 0; r < 4; ++r) {
            const int m = m0 + ih * 64 + ty * 4 + r;
#pragma unroll
            for (int jh = 0; jh < 2; ++jh) {
                const int n = n0 + jh * 64 + tx * 4;
                float4 v;
                v.x = accf[ih * 4 + r][jh * 4 + 0] + bias[n + 0];
                v.y = accf[ih * 4 + r][jh * 4 + 1] + bias[n + 1];
                v.z = accf[ih * 4 + r][jh * 4 + 2] + bias[n + 2];
                v.w = accf[ih * 4 + r][jh * 4 + 3] + bias[n + 3];
                if (splitHeads) {
                    const int b  = m >> 11;          // m / SEQ
                    const int tt = m & (SEQ - 1);
                    const int h  = n >> 6;           // n / HEAD_DIM
                    const int d  = n & (HEAD_DIM - 1);
                    *(float4*)(Y + ((b * N_HEADS + h) * SEQ + tt) * HEAD_DIM + d) = v;
                } else {
                    *(float4*)(Y + m * N + n) = v;
                }
            }
        }
    }
}

// ---------------------------------------------------------------------------
// Flash attention, causal. Q/K/V in [B*H, T, Dh] layout.
// One CTA = 64 query rows of one (b,h). 256 threads, 4x4 per thread.
// Inner products in packed f32x2. P is staged ROW-major (conflict-free
// float4 stores), consumed via broadcast loads in the PV product.
// ---------------------------------------------------------------------------
#define AP 68   // SMEM row pitch (floats)

__global__ void __launch_bounds__(256) attn_kernel(
    const float* __restrict__ Q, const float* __restrict__ K,
    const float* __restrict__ V, float* __restrict__ Y)
{
    extern __shared__ float sm[];
    float* Qs = sm;                 // [d][m]
    float* Ks = sm + 64 * AP;       // [d][n]
    float* Vs = sm + 2 * 64 * AP;   // [c][d]
    float* Ps = sm + 3 * 64 * AP;   // [m][c]  (row-major)

    const int tid = threadIdx.x;
    const int i   = tid >> 4;       // 0..15 row group
    const int j   = tid & 15;       // 0..15 col group
    const int bh  = blockIdx.y;
    const int qt  = (int)gridDim.x - 1 - (int)blockIdx.x;  // long tiles first

    // load Q tile, transposed to [d][m]
    const float* Qg = Q + (bh * SEQ + qt * 64) * HEAD_DIM;
#pragma unroll
    for (int l = 0; l < 4; ++l) {
        const int e   = tid + l * 256;       // float4 index, 0..1023
        const int row = e >> 4;
        const int d4  = (e & 15) << 2;
        float4 v = *(const float4*)(Qg + row * 64 + d4);
        Qs[(d4 + 0) * AP + row] = v.x;
        Qs[(d4 + 1) * AP + row] = v.y;
        Qs[(d4 + 2) * AP + row] = v.z;
        Qs[(d4 + 3) * AP + row] = v.w;
    }

    float mrow[4], lsum[4];
    u64 o2[4][2];                   // o2[r] = packed (c0,c1),(c2,c3)
#pragma unroll
    for (int r = 0; r < 4; ++r) {
        mrow[r] = -1e30f;
        lsum[r] = 0.0f;
        o2[r][0] = 0ull;
        o2[r][1] = 0ull;
    }

    for (int kt = 0; kt <= qt; ++kt) {
        __syncthreads();   // previous iteration done with Ks/Vs/Ps
        const float* Kg = K + (bh * SEQ + kt * 64) * HEAD_DIM;
        const float* Vg = V + (bh * SEQ + kt * 64) * HEAD_DIM;
#pragma unroll
        for (int l = 0; l < 4; ++l) {
            const int e   = tid + l * 256;
            const int row = e >> 4;
            const int d4  = (e & 15) << 2;
            float4 kv = *(const float4*)(Kg + row * 64 + d4);
            Ks[(d4 + 0) * AP + row] = kv.x;
            Ks[(d4 + 1) * AP + row] = kv.y;
            Ks[(d4 + 2) * AP + row] = kv.z;
            Ks[(d4 + 3) * AP + row] = kv.w;
            *(float4*)(Vs + row * AP + d4) = *(const float4*)(Vg + row * 64 + d4);
        }
        __syncthreads();

        // S = Q K^T, packed over row pairs
        u64 s2[2][4];
#pragma unroll
        for (int rp = 0; rp < 2; ++rp)
#pragma unroll
            for (int c = 0; c < 4; ++c) s2[rp][c] = 0ull;

#pragma unroll 16
        for (int d = 0; d < 64; ++d) {
            float4 q4 = *(const float4*)(Qs + d * AP + i * 4);
            float4 k4 = *(const float4*)(Ks + d * AP + j * 4);
            u64 qp0 = pk2(q4.x, q4.y);
            u64 qp1 = pk2(q4.z, q4.w);
            u64 kd[4] = { pk2(k4.x, k4.x), pk2(k4.y, k4.y),
                          pk2(k4.z, k4.z), pk2(k4.w, k4.w) };
#pragma unroll
            for (int c = 0; c < 4; ++c) {
                f2fma(s2[0][c], qp0, kd[c]);
                f2fma(s2[1][c], qp1, kd[c]);
            }
        }

        float s[4][4];
#pragma unroll
        for (int rp = 0; rp < 2; ++rp)
#pragma unroll
            for (int c = 0; c < 4; ++c)
                up2(s2[rp][c], s[2 * rp][c], s[2 * rp + 1][c]);

        const float sc = 0.125f;  // 1/sqrt(64)
        if (kt == qt) {
#pragma unroll
            for (int r = 0; r < 4; ++r)
#pragma unroll
                for (int c = 0; c < 4; ++c)
                    s[r][c] = ((j * 4 + c) <= (i * 4 + r)) ? s[r][c] * sc : -1e30f;
        } else {
#pragma unroll
            for (int r = 0; r < 4; ++r)
#pragma unroll
                for (int c = 0; c < 4; ++c)
                    s[r][c] *= sc;
        }

        // online softmax (row stats reduced over the 16 j-threads)
#pragma unroll
        for (int r = 0; r < 4; ++r) {
            float mx = fmaxf(fmaxf(s[r][0], s[r][1]), fmaxf(s[r][2], s[r][3]));
            mx = fmaxf(mx, __shfl_xor_sync(0xffffffffu, mx, 1));
            mx = fmaxf(mx, __shfl_xor_sync(0xffffffffu, mx, 2));
            mx = fmaxf(mx, __shfl_xor_sync(0xffffffffu, mx, 4));
            mx = fmaxf(mx, __shfl_xor_sync(0xffffffffu, mx, 8));
            const float mn   = fmaxf(mrow[r], mx);
            const float corr = __expf(mrow[r] - mn);
            mrow[r] = mn;
            float rs = 0.0f;
#pragma unroll
            for (int c = 0; c < 4; ++c) {
                float p = __expf(s[r][c] - mn);
                s[r][c] = p;
                rs += p;
            }
            rs += __shfl_xor_sync(0xffffffffu, rs, 1);
            rs += __shfl_xor_sync(0xffffffffu, rs, 2);
            rs += __shfl_xor_sync(0xffffffffu, rs, 4);
            rs += __shfl_xor_sync(0xffffffffu, rs, 8);
            lsum[r] = lsum[r] * corr + rs;
            u64 cd = pk2(corr, corr);
            f2mul(o2[r][0], cd);
            f2mul(o2[r][1], cd);
        }

        // stage P row-major: conflict-free float4 stores
#pragma unroll
        for (int r = 0; r < 4; ++r)
            *(float4*)(Ps + (i * 4 + r) * AP + j * 4) =
                make_float4(s[r][0], s[r][1], s[r][2], s[r][3]);
        __syncthreads();

        // O += P V (P rows via broadcast loads; packed over output dims)
#pragma unroll 4
        for (int c4 = 0; c4 < 16; ++c4) {
            float4 p0 = *(const float4*)(Ps + (i * 4 + 0) * AP + c4 * 4);
            float4 p1 = *(const float4*)(Ps + (i * 4 + 1) * AP + c4 * 4);
            float4 p2 = *(const float4*)(Ps + (i * 4 + 2) * AP + c4 * 4);
            float4 p3 = *(const float4*)(Ps + (i * 4 + 3) * AP + c4 * 4);
            float4 v0 = *(const float4*)(Vs + (c4 * 4 + 0) * AP + j * 4);
            float4 v1 = *(const float4*)(Vs + (c4 * 4 + 1) * AP + j * 4);
            float4 v2 = *(const float4*)(Vs + (c4 * 4 + 2) * AP + j * 4);
            float4 v3 = *(const float4*)(Vs + (c4 * 4 + 3) * AP + j * 4);
            u64 vp[4][2] = {
                { pk2(v0.x, v0.y), pk2(v0.z, v0.w) },
                { pk2(v1.x, v1.y), pk2(v1.z, v1.w) },
                { pk2(v2.x, v2.y), pk2(v2.z, v2.w) },
                { pk2(v3.x, v3.y), pk2(v3.z, v3.w) } };
            const float4 pr[4] = { p0, p1, p2, p3 };
#pragma unroll
            for (int r = 0; r < 4; ++r) {
                u64 d0 = pk2(pr[r].x, pr[r].x);
                f2fma(o2[r][0], d0, vp[0][0]);
                f2fma(o2[r][1], d0, vp[0][1]);
                u64 d1 = pk2(pr[r].y, pr[r].y);
                f2fma(o2[r][0], d1, vp[1][0]);
                f2fma(o2[r][1], d1, vp[1][1]);
                u64 d2 = pk2(pr[r].z, pr[r].z);
                f2fma(o2[r][0], d2, vp[2][0]);
                f2fma(o2[r][1], d2, vp[2][1]);
                u64 d3 = pk2(pr[r].w, pr[r].w);
                f2fma(o2[r][0], d3, vp[3][0]);
                f2fma(o2[r][1], d3, vp[3][1]);
            }
        }
    }

    // write out, merging heads: Y[b, t, h*64 + d]
    const int b = bh >> 4;
    const int h = bh & 15;
#pragma unroll
    for (int r = 0; r < 4; ++r) {
        const float inv = 1.0f / lsum[r];
        const int t = qt * 64 + i * 4 + r;
        float o0, o1, oc2, oc3;
        up2(o2[r][0], o0, o1);
        up2(o2[r][1], oc2, oc3);
        float4 outv = make_float4(o0 * inv, o1 * inv, oc2 * inv, oc3 * inv);
        *(float4*)(Y + (b * SEQ + t) * D_MODEL + h * 64 + j * 4) = outv;
    }
}

// ---------------------------------------------------------------------------
extern "C" void kernel_launch(void* const* d_in, const int* in_sizes, int n_in,
                              void* d_out, int out_size)
{
    const float* x  = (const float*)d_in[0];
    const float* Wk = (const float*)d_in[1];
    const float* bk = (const float*)d_in[2];
    const float* Wq = (const float*)d_in[3];
    const float* bq = (const float*)d_in[4];
    const float* Wv = (const float*)d_in[5];
    const float* bv = (const float*)d_in[6];
    const float* Wp = (const float*)d_in[7];
    const float* bp = (const float*)d_in[8];

    float *qp, *kp, *vp, *yp;
    cudaGetSymbolAddress((void**)&qp, g_q);
    cudaGetSymbolAddress((void**)&kp, g_k);
    cudaGetSymbolAddress((void**)&vp, g_v);
    cudaGetSymbolAddress((void**)&yp, g_y);

    const int attn_smem = 4 * 64 * AP * (int)sizeof(float);  // 69632 B
    cudaFuncSetAttribute(attn_kernel,
                         cudaFuncAttributeMaxDynamicSharedMemorySize, attn_smem);

    dim3 ggrid(D_MODEL / 128, M_ROWS / 128);   // (8, 32)
    sgemm_nt<<<ggrid, 256>>>(x, Wq, bq, qp, M_ROWS, D_MODEL, D_MODEL, 1);
    sgemm_nt<<<ggrid, 256>>>(x, Wk, bk, kp, M_ROWS, D_MODEL, D_MODEL, 1);
    sgemm_nt<<<ggrid, 256>>>(x, Wv, bv, vp, M_ROWS, D_MODEL, D_MODEL, 1);

    attn_kernel<<<dim3(SEQ / 64, BATCH * N_HEADS), 256, attn_smem>>>(qp, kp, vp, yp);

    sgemm_nt<<<ggrid, 256>>>(yp, Wp, bp, (float*)d_out, M_ROWS, D_MODEL, D_MODEL, 0);
}

// round 17
// speedup vs baseline: 1.0115x; 1.0115x over previous
#include <cuda_runtime.h>

#define D_MODEL  1024
#define N_HEADS  16
#define HEAD_DIM 64
#define SEQ      2048
#define BATCH    2
#define M_ROWS   (BATCH * SEQ)   // 4096

typedef unsigned long long u64;

// ---- packed f32x2 helpers (sm_103a dual fp32 path; ptxas never auto-emits) ----
__device__ __forceinline__ u64 pk2(float lo, float hi) {
    u64 r; asm("mov.b64 %0, {%1, %2};" : "=l"(r) : "f"(lo), "f"(hi)); return r;
}
__device__ __forceinline__ void up2(u64 v, float& lo, float& hi) {
    asm("mov.b64 {%0, %1}, %2;" : "=f"(lo), "=f"(hi) : "l"(v));
}
__device__ __forceinline__ void f2fma(u64& d, u64 a, u64 b) {
    asm("fma.rn.f32x2 %0, %1, %2, %0;" : "+l"(d) : "l"(a), "l"(b));
}
__device__ __forceinline__ void f2mul(u64& d, u64 a) {
    asm("mul.rn.f32x2 %0, %0, %1;" : "+l"(d) : "l"(a));
}

// Scratch (device globals: allocation-free per harness rules)
__device__ float g_q[M_ROWS * D_MODEL];
__device__ float g_k[M_ROWS * D_MODEL];
__device__ float g_v[M_ROWS * D_MODEL];
__device__ float g_y[M_ROWS * D_MODEL];

// ---------------------------------------------------------------------------
// NT GEMM: Y = X @ W^T + bias.   X:[M,K], W:[N,K], bias:[N]
// 128x128x8 tiles, 256 threads, 8x8 per thread, double-buffered SMEM.
// Inner product in packed f32x2: acc paired over i (adjacent in float4 A frag),
// B operand duplicated into both halves.
// ---------------------------------------------------------------------------
__global__ void __launch_bounds__(256) sgemm_nt(
    const float* __restrict__ X, const float* __restrict__ W,
    const float* __restrict__ bias, float* __restrict__ Y,
    int M, int N, int K, int splitHeads)
{
    __shared__ float As[2][8][128];
    __shared__ float Bs[2][8][128];

    const int tid = threadIdx.x;
    const int tx  = tid & 15;          // 0..15 (n groups)
    const int ty  = tid >> 4;          // 0..15 (m groups)
    const int m0  = blockIdx.y * 128;
    const int n0  = blockIdx.x * 128;

    const int lrow = tid >> 1;         // 0..127
    const int lseg = (tid & 1) * 4;    // 0 or 4

    const float* Xp = X + (m0 + lrow) * K + lseg;
    const float* Wp = W + (n0 + lrow) * K + lseg;

    float4 xa = *(const float4*)Xp;
    float4 wb = *(const float4*)Wp;

    As[0][lseg + 0][lrow] = xa.x;
    As[0][lseg + 1][lrow] = xa.y;
    As[0][lseg + 2][lrow] = xa.z;
    As[0][lseg + 3][lrow] = xa.w;
    Bs[0][lseg + 0][lrow] = wb.x;
    Bs[0][lseg + 1][lrow] = wb.y;
    Bs[0][lseg + 2][lrow] = wb.z;
    Bs[0][lseg + 3][lrow] = wb.w;
    __syncthreads();

    u64 acc2[4][8];   // acc2[ip][j] = (acc[2ip][j], acc[2ip+1][j])
#pragma unroll
    for (int ip = 0; ip < 4; ++ip)
#pragma unroll
        for (int j = 0; j < 8; ++j) acc2[ip][j] = 0ull;

    const int ntiles = K >> 3;
    int buf = 0;
    for (int t = 0; t < ntiles; ++t) {
        if (t + 1 < ntiles) {
            xa = *(const float4*)(Xp + (t + 1) * 8);
            wb = *(const float4*)(Wp + (t + 1) * 8);
        }
#pragma unroll
        for (int k = 0; k < 8; ++k) {
            float4 a0 = *(const float4*)(&As[buf][k][ty * 4]);
            float4 a1 = *(const float4*)(&As[buf][k][ty * 4 + 64]);
            float4 b0 = *(const float4*)(&Bs[buf][k][tx * 4]);
            float4 b1 = *(const float4*)(&Bs[buf][k][tx * 4 + 64]);
            u64 ap[4] = { pk2(a0.x, a0.y), pk2(a0.z, a0.w),
                          pk2(a1.x, a1.y), pk2(a1.z, a1.w) };
            u64 bd[8] = { pk2(b0.x, b0.x), pk2(b0.y, b0.y),
                          pk2(b0.z, b0.z), pk2(b0.w, b0.w),
                          pk2(b1.x, b1.x), pk2(b1.y, b1.y),
                          pk2(b1.z, b1.z), pk2(b1.w, b1.w) };
#pragma unroll
            for (int ip = 0; ip < 4; ++ip)
#pragma unroll
                for (int j = 0; j < 8; ++j)
                    f2fma(acc2[ip][j], ap[ip], bd[j]);
        }
        if (t + 1 < ntiles) {
            buf ^= 1;
            As[buf][lseg + 0][lrow] = xa.x;
            As[buf][lseg + 1][lrow] = xa.y;
            As[buf][lseg + 2][lrow] = xa.z;
            As[buf][lseg + 3][lrow] = xa.w;
            Bs[buf][lseg + 0][lrow] = wb.x;
            Bs[buf][lseg + 1][lrow] = wb.y;
            Bs[buf][lseg + 2][lrow] = wb.z;
            Bs[buf][lseg + 3][lrow] = wb.w;
            __syncthreads();
        }
    }

    // unpack accumulators
    float accf[8][8];
#pragma unroll
    for (int ip = 0; ip < 4; ++ip)
#pragma unroll
        for (int j = 0; j < 8; ++j)
            up2(acc2[ip][j], accf[2 * ip][j], accf[2 * ip + 1][j]);

    // epilogue
#pragma unroll
    for (int ih = 0; ih < 2; ++ih) {
#pragma unroll
        for (int r = 0; r < 4; ++r) {
            const int m = m0 + ih * 64 + ty * 4 + r;
#pragma unroll
            for (int jh = 0; jh < 2; ++jh) {
                const int n = n0 + jh * 64 + tx * 4;
                float4 v;
                v.x = accf[ih * 4 + r][jh * 4 + 0] + bias[n + 0];
                v.y = accf[ih * 4 + r][jh * 4 + 1] + bias[n + 1];
                v.z = accf[ih * 4 + r][jh * 4 + 2] + bias[n + 2];
                v.w = accf[ih * 4 + r][jh * 4 + 3] + bias[n + 3];
                if (splitHeads) {
                    const int b  = m >> 11;          // m / SEQ
                    const int tt = m & (SEQ - 1);
                    const int h  = n >> 6;           // n / HEAD_DIM
                    const int d  = n & (HEAD_DIM - 1);
                    *(float4*)(Y + ((b * N_HEADS + h) * SEQ + tt) * HEAD_DIM + d) = v;
                } else {
                    *(float4*)(Y + m * N + n) = v;
                }
            }
        }
    }
}

// ---------------------------------------------------------------------------
// Flash attention, causal. Q/K/V in [B*H, T, Dh] layout.
// One CTA = 64 query rows of one (b,h). 256 threads, 4x4 per thread.
// Inner products in packed f32x2. P is staged ROW-major (conflict-free
// float4 stores), consumed via broadcast loads in the PV product.
// ---------------------------------------------------------------------------
#define AP 68   // SMEM row pitch (floats)

__global__ void __launch_bounds__(256) attn_kernel(
    const float* __restrict__ Q, const float* __restrict__ K,
    const float* __restrict__ V, float* __restrict__ Y)
{
    extern __shared__ float sm[];
    float* Qs = sm;                 // [d][m]
    float* Ks = sm + 64 * AP;       // [d][n]
    float* Vs = sm + 2 * 64 * AP;   // [c][d]
    float* Ps = sm + 3 * 64 * AP;   // [m][c]  (row-major)

    const int tid = threadIdx.x;
    const int i   = tid >> 4;       // 0..15 row group
    const int j   = tid & 15;       // 0..15 col group
    const int bh  = blockIdx.y;
    const int qt  = (int)gridDim.x - 1 - (int)blockIdx.x;  // long tiles first

    // load Q tile, transposed to [d][m]
    const float* Qg = Q + (bh * SEQ + qt * 64) * HEAD_DIM;
#pragma unroll
    for (int l = 0; l < 4; ++l) {
        const int e   = tid + l * 256;       // float4 index, 0..1023
        const int row = e >> 4;
        const int d4  = (e & 15) << 2;
        float4 v = *(const float4*)(Qg + row * 64 + d4);
        Qs[(d4 + 0) * AP + row] = v.x;
        Qs[(d4 + 1) * AP + row] = v.y;
        Qs[(d4 + 2) * AP + row] = v.z;
        Qs[(d4 + 3) * AP + row] = v.w;
    }

    float mrow[4], lsum[4];
    u64 o2[4][2];                   // o2[r] = packed (c0,c1),(c2,c3)
#pragma unroll
    for (int r = 0; r < 4; ++r) {
        mrow[r] = -1e30f;
        lsum[r] = 0.0f;
        o2[r][0] = 0ull;
        o2[r][1] = 0ull;
    }

    for (int kt = 0; kt <= qt; ++kt) {
        __syncthreads();   // previous iteration done with Ks/Vs/Ps
        const float* Kg = K + (bh * SEQ + kt * 64) * HEAD_DIM;
        const float* Vg = V + (bh * SEQ + kt * 64) * HEAD_DIM;
#pragma unroll
        for (int l = 0; l < 4; ++l) {
            const int e   = tid + l * 256;
            const int row = e >> 4;
            const int d4  = (e & 15) << 2;
            float4 kv = *(const float4*)(Kg + row * 64 + d4);
            Ks[(d4 + 0) * AP + row] = kv.x;
            Ks[(d4 + 1) * AP + row] = kv.y;
            Ks[(d4 + 2) * AP + row] = kv.z;
            Ks[(d4 + 3) * AP + row] = kv.w;
            *(float4*)(Vs + row * AP + d4) = *(const float4*)(Vg + row * 64 + d4);
        }
        __syncthreads();

        // S = Q K^T, packed over row pairs
        u64 s2[2][4];
#pragma unroll
        for (int rp = 0; rp < 2; ++rp)
#pragma unroll
            for (int c = 0; c < 4; ++c) s2[rp][c] = 0ull;

#pragma unroll 16
        for (int d = 0; d < 64; ++d) {
            float4 q4 = *(const float4*)(Qs + d * AP + i * 4);
            float4 k4 = *(const float4*)(Ks + d * AP + j * 4);
            u64 qp0 = pk2(q4.x, q4.y);
            u64 qp1 = pk2(q4.z, q4.w);
            u64 kd[4] = { pk2(k4.x, k4.x), pk2(k4.y, k4.y),
                          pk2(k4.z, k4.z), pk2(k4.w, k4.w) };
#pragma unroll
            for (int c = 0; c < 4; ++c) {
                f2fma(s2[0][c], qp0, kd[c]);
                f2fma(s2[1][c], qp1, kd[c]);
            }
        }

        float s[4][4];
#pragma unroll
        for (int rp = 0; rp < 2; ++rp)
#pragma unroll
            for (int c = 0; c < 4; ++c)
                up2(s2[rp][c], s[2 * rp][c], s[2 * rp + 1][c]);

        const float sc = 0.125f;  // 1/sqrt(64)
        if (kt == qt) {
#pragma unroll
            for (int r = 0; r < 4; ++r)
#pragma unroll
                for (int c = 0; c < 4; ++c)
                    s[r][c] = ((j * 4 + c) <= (i * 4 + r)) ? s[r][c] * sc : -1e30f;
        } else {
#pragma unroll
            for (int r = 0; r < 4; ++r)
#pragma unroll
                for (int c = 0; c < 4; ++c)
                    s[r][c] *= sc;
        }

        // online softmax (row stats reduced over the 16 j-threads)
#pragma unroll
        for (int r = 0; r < 4; ++r) {
            float mx = fmaxf(fmaxf(s[r][0], s[r][1]), fmaxf(s[r][2], s[r][3]));
            mx = fmaxf(mx, __shfl_xor_sync(0xffffffffu, mx, 1));
            mx = fmaxf(mx, __shfl_xor_sync(0xffffffffu, mx, 2));
            mx = fmaxf(mx, __shfl_xor_sync(0xffffffffu, mx, 4));
            mx = fmaxf(mx, __shfl_xor_sync(0xffffffffu, mx, 8));
            const float mn   = fmaxf(mrow[r], mx);
            const float corr = __expf(mrow[r] - mn);
            mrow[r] = mn;
            float rs = 0.0f;
#pragma unroll
            for (int c = 0; c < 4; ++c) {
                float p = __expf(s[r][c] - mn);
                s[r][c] = p;
                rs += p;
            }
            rs += __shfl_xor_sync(0xffffffffu, rs, 1);
            rs += __shfl_xor_sync(0xffffffffu, rs, 2);
            rs += __shfl_xor_sync(0xffffffffu, rs, 4);
            rs += __shfl_xor_sync(0xffffffffu, rs, 8);
            lsum[r] = lsum[r] * corr + rs;
            u64 cd = pk2(corr, corr);
            f2mul(o2[r][0], cd);
            f2mul(o2[r][1], cd);
        }

        // stage P row-major: conflict-free float4 stores
#pragma unroll
        for (int r = 0; r < 4; ++r)
            *(float4*)(Ps + (i * 4 + r) * AP + j * 4) =
                make_float4(s[r][0], s[r][1], s[r][2], s[r][3]);
        __syncthreads();

        // O += P V (P rows via broadcast loads; packed over output dims)
#pragma unroll 4
        for (int c4 = 0; c4 < 16; ++c4) {
            float4 p0 = *(const float4*)(Ps + (i * 4 + 0) * AP + c4 * 4);
            float4 p1 = *(const float4*)(Ps + (i * 4 + 1) * AP + c4 * 4);
            float4 p2 = *(const float4*)(Ps + (i * 4 + 2) * AP + c4 * 4);
            float4 p3 = *(const float4*)(Ps + (i * 4 + 3) * AP + c4 * 4);
            float4 v0 = *(const float4*)(Vs + (c4 * 4 + 0) * AP + j * 4);
            float4 v1 = *(const float4*)(Vs + (c4 * 4 + 1) * AP + j * 4);
            float4 v2 = *(const float4*)(Vs + (c4 * 4 + 2) * AP + j * 4);
            float4 v3 = *(const float4*)(Vs + (c4 * 4 + 3) * AP + j * 4);
            u64 vp[4][2] = {
                { pk2(v0.x, v0.y), pk2(v0.z, v0.w) },
                { pk2(v1.x, v1.y), pk2(v1.z, v1.w) },
                { pk2(v2.x, v2.y), pk2(v2.z, v2.w) },
                { pk2(v3.x, v3.y), pk2(v3.z, v3.w) } };
            const float4 pr[4] = { p0, p1, p2, p3 };
#pragma unroll
            for (int r = 0; r < 4; ++r) {
                u64 d0 = pk2(pr[r].x, pr[r].x);
                f2fma(o2[r][0], d0, vp[0][0]);
                f2fma(o2[r][1], d0, vp[0][1]);
                u64 d1 = pk2(pr[r].y, pr[r].y);
                f2fma(o2[r][0], d1, vp[1][0]);
                f2fma(o2[r][1], d1, vp[1][1]);
                u64 d2 = pk2(pr[r].z, pr[r].z);
                f2fma(o2[r][0], d2, vp[2][0]);
                f2fma(o2[r][1], d2, vp[2][1]);
                u64 d3 = pk2(pr[r].w, pr[r].w);
                f2fma(o2[r][0], d3, vp[3][0]);
                f2fma(o2[r][1], d3, vp[3][1]);
            }
        }
    }

    // write out, merging heads: Y[b, t, h*64 + d]
    const int b = bh >> 4;
    const int h = bh & 15;
#pragma unroll
    for (int r = 0; r < 4; ++r) {
        const float inv = 1.0f / lsum[r];
        const int t = qt * 64 + i * 4 + r;
        float o0, o1, oc2, oc3;
        up2(o2[r][0], o0, o1);
        up2(o2[r][1], oc2, oc3);
        float4 outv = make_float4(o0 * inv, o1 * inv, oc2 * inv, oc3 * inv);
        *(float4*)(Y + (b * SEQ + t) * D_MODEL + h * 64 + j * 4) = outv;
    }
}

// ---------------------------------------------------------------------------
extern "C" void kernel_launch(void* const* d_in, const int* in_sizes, int n_in,
                              void* d_out, int out_size)
{
    const float* x  = (const float*)d_in[0];
    const float* Wk = (const float*)d_in[1];
    const float* bk = (const float*)d_in[2];
    const float* Wq = (const float*)d_in[3];
    const float* bq = (const float*)d_in[4];
    const float* Wv = (const float*)d_in[5];
    const float* bv = (const float*)d_in[6];
    const float* Wp = (const float*)d_in[7];
    const float* bp = (const float*)d_in[8];

    float *qp, *kp, *vp, *yp;
    cudaGetSymbolAddress((void**)&qp, g_q);
    cudaGetSymbolAddress((void**)&kp, g_k);
    cudaGetSymbolAddress((void**)&vp, g_v);
    cudaGetSymbolAddress((void**)&yp, g_y);

    const int attn_smem = 4 * 64 * AP * (int)sizeof(float);  // 69632 B
    cudaFuncSetAttribute(attn_kernel,
                         cudaFuncAttributeMaxDynamicSharedMemorySize, attn_smem);

    dim3 ggrid(D_MODEL / 128, M_ROWS / 128);   // (8, 32)
    sgemm_nt<<<ggrid, 256>>>(x, Wq, bq, qp, M_ROWS, D_MODEL, D_MODEL, 1);
    sgemm_nt<<<ggrid, 256>>>(x, Wk, bk, kp, M_ROWS, D_MODEL, D_MODEL, 1);
    sgemm_nt<<<ggrid, 256>>>(x, Wv, bv, vp, M_ROWS, D_MODEL, D_MODEL, 1);

    attn_kernel<<<dim3(SEQ / 64, BATCH * N_HEADS), 256, attn_smem>>>(qp, kp, vp, yp);

    sgemm_nt<<<ggrid, 256>>>(yp, Wp, bp, (float*)d_out, M_ROWS, D_MODEL, D_MODEL, 0);
}